// round 1
// baseline (speedup 1.0000x reference)
#include <cuda_runtime.h>
#include <cuda_bf16.h>
#include <cstdint>

#define NB 8192
#define ND 256
#define NK 8
#define NT 64            // 128-wide tiles per matrix dim
#define LOG2E_F 1.4426950408889634f
#define LN2_F   0.6931471805599453f

// ---------------- device scratch (static: no allocation allowed) ----------------
__device__ __align__(16) __nv_bfloat16 g_z[NB * ND];        // normalized embeddings, bf16
__device__ float g_Apart[NT * NB];                          // per-(colTile,row) partial sum of e^s
__device__ float g_Bpart[NT * NB];                          // per-(colTile,row) partial sum of u*e^s (base-2 u)
__device__ float g_uPos[NB * NK];                           // u at positive entries
__device__ float g_uDiag[NB];                               // u at diagonal
__device__ float g_logDenom[NB];
__device__ unsigned g_negMinK, g_negMaxK, g_pvMinK, g_pvMaxK;
__device__ float g_C1;                                      // log2(e)/softplus(temp)

// ---------------- helpers ----------------
__device__ __forceinline__ unsigned enc(float f) {
    unsigned b = __float_as_uint(f);
    return (b & 0x80000000u) ? ~b : (b | 0x80000000u);      // monotone float->uint key
}
__device__ __forceinline__ float dec(unsigned k) {
    unsigned b = (k & 0x80000000u) ? (k ^ 0x80000000u) : ~k;
    return __uint_as_float(b);
}
__device__ __forceinline__ float ex2(float x) {
    float y; asm("ex2.approx.ftz.f32 %0, %1;" : "=f"(y) : "f"(x)); return y;
}
__device__ __forceinline__ void mma16816(float* d, const unsigned* a, const unsigned* b) {
    asm volatile(
        "mma.sync.aligned.m16n8k16.row.col.f32.bf16.bf16.f32 "
        "{%0,%1,%2,%3}, {%4,%5,%6,%7}, {%8,%9}, {%0,%1,%2,%3};\n"
        : "+f"(d[0]), "+f"(d[1]), "+f"(d[2]), "+f"(d[3])
        : "r"(a[0]), "r"(a[1]), "r"(a[2]), "r"(a[3]), "r"(b[0]), "r"(b[1]));
}

// ---------------- kernel 0: scalars + atomic resets ----------------
__global__ void k_init(const float* __restrict__ temperature) {
    float t = temperature[0];
    float sp = (t > 20.f) ? t : log1pf(expf(t));            // softplus
    g_C1 = LOG2E_F / sp;
    g_negMinK = 0xFFFFFFFFu; g_negMaxK = 0u;
    g_pvMinK  = 0xFFFFFFFFu; g_pvMaxK  = 0u;
}

// ---------------- kernel 1: L2-normalize rows, emit bf16 ----------------
__global__ void k_norm(const float* __restrict__ emb) {
    int row  = blockIdx.x * 8 + (threadIdx.x >> 5);
    int lane = threadIdx.x & 31;
    const float4* src = (const float4*)(emb + (size_t)row * ND);
    float4 v0 = src[lane * 2], v1 = src[lane * 2 + 1];
    float ss = v0.x*v0.x + v0.y*v0.y + v0.z*v0.z + v0.w*v0.w
             + v1.x*v1.x + v1.y*v1.y + v1.z*v1.z + v1.w*v1.w;
    #pragma unroll
    for (int off = 16; off; off >>= 1) ss += __shfl_xor_sync(0xffffffffu, ss, off);
    float inv = 1.f / fmaxf(sqrtf(ss), 1e-12f);
    __nv_bfloat162 o[4];
    o[0] = __floats2bfloat162_rn(v0.x*inv, v0.y*inv);
    o[1] = __floats2bfloat162_rn(v0.z*inv, v0.w*inv);
    o[2] = __floats2bfloat162_rn(v1.x*inv, v1.y*inv);
    o[3] = __floats2bfloat162_rn(v1.z*inv, v1.w*inv);
    *(uint4*)(g_z + (size_t)row * ND + lane * 8) = *(const uint4*)o;
}

// ---------------- kernel 2: min/max of pos_vals ----------------
__global__ void k_pvmm(const float* __restrict__ pv) {
    int i0 = (blockIdx.x * 256 + threadIdx.x) * 4;
    float4 v = *(const float4*)(pv + i0);
    float mn = fminf(fminf(v.x, v.y), fminf(v.z, v.w));
    float mx = fmaxf(fmaxf(v.x, v.y), fmaxf(v.z, v.w));
    #pragma unroll
    for (int off = 16; off; off >>= 1) {
        mn = fminf(mn, __shfl_xor_sync(0xffffffffu, mn, off));
        mx = fmaxf(mx, __shfl_xor_sync(0xffffffffu, mx, off));
    }
    __shared__ float smn[8], smx[8];
    int w = threadIdx.x >> 5;
    if ((threadIdx.x & 31) == 0) { smn[w] = mn; smx[w] = mx; }
    __syncthreads();
    if (threadIdx.x == 0) {
        float a = smn[0], b = smx[0];
        #pragma unroll
        for (int i = 1; i < 8; i++) { a = fminf(a, smn[i]); b = fmaxf(b, smx[i]); }
        atomicMin(&g_pvMinK, enc(a));
        atomicMax(&g_pvMaxK, enc(b));
    }
}

// ---------------- kernel 3: fused GEMM (bf16 mma.sync) + exp-sum epilogue ----------------
__global__ __launch_bounds__(256, 2) void k_main() {
    const int rt = blockIdx.y, ct = blockIdx.x;
    const bool band = (((ct - rt) & (NT - 1)) <= 1);        // tile touches pos/diag band?

    __shared__ __align__(16) __nv_bfloat16 sA[128][72];     // +8 pad: conflict-free frag loads
    __shared__ __align__(16) __nv_bfloat16 sB[128][72];
    __shared__ float sRowA[2][128], sRowB[2][128];
    __shared__ float sMin[8], sMax[8];

    const int tid  = threadIdx.x;
    const int w    = tid >> 5, lane = tid & 31;
    const int wr   = w >> 1,   wc   = w & 1;                // warp grid 4x2, warp tile 32x64
    const int g    = lane >> 2, c   = lane & 3;

    float acc[2][8][4];
    #pragma unroll
    for (int mi = 0; mi < 2; mi++)
        #pragma unroll
        for (int ni = 0; ni < 8; ni++)
            #pragma unroll
            for (int q = 0; q < 4; q++) acc[mi][ni][q] = 0.f;

    for (int kc = 0; kc < 4; kc++) {                        // K chunks of 64
        const int k0 = kc * 64;
        #pragma unroll
        for (int it = 0; it < 4; it++) {
            int idx = tid + it * 256;                       // 1024 uint4 per tile
            int row = idx >> 3, q = idx & 7;
            *(uint4*)&sA[row][q * 8] =
                *(const uint4*)(g_z + ((size_t)(rt * 128 + row)) * ND + k0 + q * 8);
            *(uint4*)&sB[row][q * 8] =
                *(const uint4*)(g_z + ((size_t)(ct * 128 + row)) * ND + k0 + q * 8);
        }
        __syncthreads();
        #pragma unroll
        for (int ks = 0; ks < 4; ks++) {
            const int kk = ks * 16;
            unsigned af[2][4], bfr[8][2];
            #pragma unroll
            for (int mi = 0; mi < 2; mi++) {
                int r0 = wr * 32 + mi * 16 + g;
                af[mi][0] = *(const unsigned*)&sA[r0    ][kk + 2 * c];
                af[mi][1] = *(const unsigned*)&sA[r0 + 8][kk + 2 * c];
                af[mi][2] = *(const unsigned*)&sA[r0    ][kk + 2 * c + 8];
                af[mi][3] = *(const unsigned*)&sA[r0 + 8][kk + 2 * c + 8];
            }
            #pragma unroll
            for (int ni = 0; ni < 8; ni++) {
                int n0 = wc * 64 + ni * 8 + g;
                bfr[ni][0] = *(const unsigned*)&sB[n0][kk + 2 * c];
                bfr[ni][1] = *(const unsigned*)&sB[n0][kk + 2 * c + 8];
            }
            #pragma unroll
            for (int mi = 0; mi < 2; mi++)
                #pragma unroll
                for (int ni = 0; ni < 8; ni++)
                    mma16816(acc[mi][ni], af[mi], bfr[ni]);
        }
        __syncthreads();
    }

    // ---- epilogue: u = (d-1)/temp * log2(e); e = 2^u; row sums of e, u*e; neg min/max ----
    const float C1 = g_C1;
    float rA[4] = {0,0,0,0}, rB[4] = {0,0,0,0};
    float umin = __int_as_float(0x7f800000);
    float umax = __int_as_float(0xff800000);
    const int rowBase = rt * 128 + wr * 32;
    const int colBase = ct * 128 + wc * 64;
    #pragma unroll
    for (int mi = 0; mi < 2; mi++)
    #pragma unroll
    for (int p = 0; p < 2; p++) {
        const int ai = mi * 2 + p;
        const int iG = rowBase + mi * 16 + p * 8 + g;
        #pragma unroll
        for (int ni = 0; ni < 8; ni++)
        #pragma unroll
        for (int q = 0; q < 2; q++) {
            float d = acc[mi][ni][p * 2 + q];
            float u = __fmaf_rn(d, C1, -C1);
            float e = ex2(u);
            rA[ai] += e;
            rB[ai] = __fmaf_rn(u, e, rB[ai]);
            if (!band) {
                umin = fminf(umin, u); umax = fmaxf(umax, u);
            } else {
                int jG = colBase + ni * 8 + 2 * c + q;
                int dd = (jG - iG) & (NB - 1);
                if (dd > NK)      { umin = fminf(umin, u); umax = fmaxf(umax, u); }
                else if (dd == 0) g_uDiag[iG] = u;
                else              g_uPos[iG * NK + dd - 1] = u;
            }
        }
    }
    // reduce A/B across the 4 lanes sharing a row (c = 0..3)
    #pragma unroll
    for (int ai = 0; ai < 4; ai++) {
        float a = rA[ai], b = rB[ai];
        a += __shfl_xor_sync(0xffffffffu, a, 1); a += __shfl_xor_sync(0xffffffffu, a, 2);
        b += __shfl_xor_sync(0xffffffffu, b, 1); b += __shfl_xor_sync(0xffffffffu, b, 2);
        if (c == 0) {
            int rloc = wr * 32 + (ai >> 1) * 16 + (ai & 1) * 8 + g;
            sRowA[wc][rloc] = a; sRowB[wc][rloc] = b;
        }
    }
    #pragma unroll
    for (int off = 16; off; off >>= 1) {
        umin = fminf(umin, __shfl_xor_sync(0xffffffffu, umin, off));
        umax = fmaxf(umax, __shfl_xor_sync(0xffffffffu, umax, off));
    }
    if (lane == 0) { sMin[w] = umin; sMax[w] = umax; }
    __syncthreads();
    if (tid < 128) {
        g_Apart[ct * NB + rt * 128 + tid] = sRowA[0][tid] + sRowA[1][tid];
        g_Bpart[ct * NB + rt * 128 + tid] = sRowB[0][tid] + sRowB[1][tid];
    }
    if (tid == 0) {
        float mn = sMin[0], mx = sMax[0];
        #pragma unroll
        for (int i = 1; i < 8; i++) { mn = fminf(mn, sMin[i]); mx = fmaxf(mx, sMax[i]); }
        atomicMin(&g_negMinK, enc(mn));
        atomicMax(&g_negMaxK, enc(mx));
    }
}

// ---------------- kernel 4: per-row log(denominator) ----------------
__global__ void k_fin1() {
    int i = blockIdx.x * 128 + threadIdx.x;
    float A = 0.f, Bp = 0.f;
    #pragma unroll 8
    for (int ctile = 0; ctile < NT; ctile++) {
        A  += g_Apart[ctile * NB + i];
        Bp += g_Bpart[ctile * NB + i];
    }
    float Bn   = Bp * LN2_F;                                // natural-log weighted sum
    float nmin = dec(g_negMinK) * LN2_F;
    float nmax = dec(g_negMaxK) * LN2_F;
    float uD = g_uDiag[i];
    float eD = ex2(uD);
    float sumE = eD, sumSE = uD * LN2_F * eD;
    #pragma unroll
    for (int k = 0; k < NK; k++) {
        float u = g_uPos[i * NK + k];
        float e = ex2(u);
        sumE  += e;
        sumSE += u * LN2_F * e;
    }
    float Aneg = A - sumE;
    float Bneg = Bn - sumSE;
    float denom = A + (Bneg - nmin * Aneg) / (nmax - nmin + 1e-8f);
    g_logDenom[i] = logf(denom);
}

// ---------------- kernel 5: weighted mean over positives ----------------
__global__ void k_fin2(const float* __restrict__ pv, float* __restrict__ out) {
    float pvMax = dec(g_pvMaxK), pvMin = dec(g_pvMinK);
    float invPr = 1.f / ((pvMax - pvMin) + 1e-8f);
    float acc = 0.f;
    for (int e = threadIdx.x; e < NB * NK; e += 256) {
        int i = e >> 3;
        float pw = (pvMax - pv[e]) * invPr;                 // min-max normalized (1 - v)
        float pl = g_uPos[e] * LN2_F - g_logDenom[i];       // log prob at positive
        acc += pl * pw;
    }
    #pragma unroll
    for (int off = 16; off; off >>= 1) acc += __shfl_xor_sync(0xffffffffu, acc, off);
    __shared__ float sp[8];
    int w = threadIdx.x >> 5;
    if ((threadIdx.x & 31) == 0) sp[w] = acc;
    __syncthreads();
    if (threadIdx.x == 0) {
        float t = 0.f;
        #pragma unroll
        for (int i = 0; i < 8; i++) t += sp[i];
        out[0] = -t * (1.f / (NB * NK));
    }
}

// ---------------- launch ----------------
extern "C" void kernel_launch(void* const* d_in, const int* in_sizes, int n_in,
                              void* d_out, int out_size) {
    const float* emb  = (const float*)d_in[0];
    const float* pv   = (const float*)d_in[1];
    const float* temp = (const float*)d_in[2];
    float* out = (float*)d_out;
    (void)in_sizes; (void)n_in; (void)out_size;

    k_init<<<1, 1>>>(temp);
    k_norm<<<NB / 8, 256>>>(emb);
    k_pvmm<<<NB * NK / (256 * 4), 256>>>(pv);
    k_main<<<dim3(NT, NT), 256>>>();
    k_fin1<<<NB / 128, 128>>>();
    k_fin2<<<1, 256>>>(pv, out);
}

// round 2
// speedup vs baseline: 1.7107x; 1.7107x over previous
#include <cuda_runtime.h>
#include <cuda_bf16.h>
#include <cstdint>

#define NB 8192
#define ND 256
#define NK 8
#define NT 64            // 128-wide tiles per matrix dim
#define LOG2E_F 1.4426950408889634f
#define LN2_F   0.6931471805599453f
#define CH 32            // K chunk per pipeline stage
#define SROW 40          // padded bf16 row length per chunk buffer (80B: conflict-free ldmatrix)
#define BUFB (128 * SROW * 2)   // bytes per buffer per matrix

// ---------------- device scratch (static: no allocation allowed) ----------------
__device__ __align__(16) __nv_bfloat16 g_z[NB * ND];        // normalized embeddings, bf16
__device__ float g_Apart[NT * NB];                          // per-(slot,row) partial sum of e^u
__device__ float g_Bpart[NT * NB];                          // per-(slot,row) partial sum of u*e^u
__device__ float g_uPos[NB * NK];                           // u at positive entries
__device__ float g_uDiag[NB];                               // u at diagonal
__device__ float g_red[NB / 128];                           // per-block weighted-sum partials
__device__ unsigned g_negMinK, g_negMaxK, g_pvMinK, g_pvMaxK;
__device__ float g_C1;                                      // log2(e)/softplus(temp)

// ---------------- helpers ----------------
__device__ __forceinline__ unsigned enc(float f) {
    unsigned b = __float_as_uint(f);
    return (b & 0x80000000u) ? ~b : (b | 0x80000000u);      // monotone float->uint key
}
__device__ __forceinline__ float dec(unsigned k) {
    unsigned b = (k & 0x80000000u) ? (k ^ 0x80000000u) : ~k;
    return __uint_as_float(b);
}
__device__ __forceinline__ float ex2(float x) {
    float y; asm("ex2.approx.ftz.f32 %0, %1;" : "=f"(y) : "f"(x)); return y;
}
__device__ __forceinline__ void mma16816(float* d, const unsigned* a, const unsigned* b) {
    asm volatile(
        "mma.sync.aligned.m16n8k16.row.col.f32.bf16.bf16.f32 "
        "{%0,%1,%2,%3}, {%4,%5,%6,%7}, {%8,%9}, {%0,%1,%2,%3};\n"
        : "+f"(d[0]), "+f"(d[1]), "+f"(d[2]), "+f"(d[3])
        : "r"(a[0]), "r"(a[1]), "r"(a[2]), "r"(a[3]), "r"(b[0]), "r"(b[1]));
}
__device__ __forceinline__ void ldsm4(unsigned& r0, unsigned& r1, unsigned& r2, unsigned& r3,
                                      unsigned addr) {
    asm volatile("ldmatrix.sync.aligned.m8n8.x4.shared.b16 {%0,%1,%2,%3}, [%4];\n"
                 : "=r"(r0), "=r"(r1), "=r"(r2), "=r"(r3) : "r"(addr));
}
__device__ __forceinline__ void cpasync16(unsigned daddr, const void* src) {
    asm volatile("cp.async.cg.shared.global [%0], [%1], 16;\n" :: "r"(daddr), "l"(src));
}
__device__ __forceinline__ void cpcommit() { asm volatile("cp.async.commit_group;\n"); }
template <int N> __device__ __forceinline__ void cpwait() {
    asm volatile("cp.async.wait_group %0;\n" :: "n"(N));
}

// ---------------- kernel 0: scalars + atomic resets ----------------
__global__ void k_init(const float* __restrict__ temperature) {
    float t = temperature[0];
    float sp = (t > 20.f) ? t : log1pf(expf(t));            // softplus
    g_C1 = LOG2E_F / sp;
    g_negMinK = 0xFFFFFFFFu; g_negMaxK = 0u;
    g_pvMinK  = 0xFFFFFFFFu; g_pvMaxK  = 0u;
}

// ---------------- kernel 1: L2-normalize rows, emit bf16 ----------------
__global__ void k_norm(const float* __restrict__ emb) {
    int row  = blockIdx.x * 8 + (threadIdx.x >> 5);
    int lane = threadIdx.x & 31;
    const float4* src = (const float4*)(emb + (size_t)row * ND);
    float4 v0 = src[lane * 2], v1 = src[lane * 2 + 1];
    float ss = v0.x*v0.x + v0.y*v0.y + v0.z*v0.z + v0.w*v0.w
             + v1.x*v1.x + v1.y*v1.y + v1.z*v1.z + v1.w*v1.w;
    #pragma unroll
    for (int off = 16; off; off >>= 1) ss += __shfl_xor_sync(0xffffffffu, ss, off);
    float inv = 1.f / fmaxf(sqrtf(ss), 1e-12f);
    __nv_bfloat162 o[4];
    o[0] = __floats2bfloat162_rn(v0.x*inv, v0.y*inv);
    o[1] = __floats2bfloat162_rn(v0.z*inv, v0.w*inv);
    o[2] = __floats2bfloat162_rn(v1.x*inv, v1.y*inv);
    o[3] = __floats2bfloat162_rn(v1.z*inv, v1.w*inv);
    *(uint4*)(g_z + (size_t)row * ND + lane * 8) = *(const uint4*)o;
}

// ---------------- kernel 2: min/max of pos_vals ----------------
__global__ void k_pvmm(const float* __restrict__ pv) {
    int i0 = (blockIdx.x * 256 + threadIdx.x) * 4;
    float4 v = *(const float4*)(pv + i0);
    float mn = fminf(fminf(v.x, v.y), fminf(v.z, v.w));
    float mx = fmaxf(fmaxf(v.x, v.y), fmaxf(v.z, v.w));
    #pragma unroll
    for (int off = 16; off; off >>= 1) {
        mn = fminf(mn, __shfl_xor_sync(0xffffffffu, mn, off));
        mx = fmaxf(mx, __shfl_xor_sync(0xffffffffu, mx, off));
    }
    __shared__ float smn[8], smx[8];
    int w = threadIdx.x >> 5;
    if ((threadIdx.x & 31) == 0) { smn[w] = mn; smx[w] = mx; }
    __syncthreads();
    if (threadIdx.x == 0) {
        float a = smn[0], b = smx[0];
        #pragma unroll
        for (int i = 1; i < 8; i++) { a = fminf(a, smn[i]); b = fmaxf(b, smx[i]); }
        atomicMin(&g_pvMinK, enc(a));
        atomicMax(&g_pvMaxK, enc(b));
    }
}

// ---------------- kernel 3: symmetric fused GEMM + exp-sum epilogue ----------------
// Only tiles with ct >= rt are computed; each exp feeds both its row-sum (rows of
// rt-block, slot ct) and, for off-diagonal tiles, its column-sum (rows of ct-block,
// slot rt). Every row's 64 partial slots are written exactly once -> deterministic.
__global__ __launch_bounds__(256, 2) void k_main() {
    const int rt = blockIdx.y, ct = blockIdx.x;
    if (ct < rt) return;
    const bool isDiag = (rt == ct);
    const bool band = (((ct - rt) & (NT - 1)) <= 1) || (((rt - ct) & (NT - 1)) == 1);

    __shared__ __align__(16) __nv_bfloat16 sA[2][128][SROW];
    __shared__ __align__(16) __nv_bfloat16 sB[2][128][SROW];
    __shared__ float sRowA[2][128], sRowB[2][128];
    __shared__ float sColA[4][128], sColB[4][128];
    __shared__ float sMin[8], sMax[8];

    const int tid  = threadIdx.x;
    const int w    = tid >> 5, lane = tid & 31;
    const int wr   = w >> 1,   wc   = w & 1;                // warp grid 4x2, warp tile 32x64
    const int g    = lane >> 2, c   = lane & 3;

    // ldmatrix lane addressing (precomputed; per-chunk offset added later)
    unsigned aAddr[2], bAddr[4];
    {
        int rowA = wr * 32 + (lane & 15);
        int colA = (lane >> 4) * 8;
        aAddr[0] = (unsigned)__cvta_generic_to_shared(&sA[0][rowA][colA]);
        aAddr[1] = aAddr[0] + 16 * SROW * 2;
        int rowB = wc * 64 + (lane & 7) + ((lane & 16) ? 8 : 0);
        int colB = ((lane >> 3) & 1) * 8;
        unsigned b0 = (unsigned)__cvta_generic_to_shared(&sB[0][rowB][colB]);
        #pragma unroll
        for (int nj = 0; nj < 4; nj++) bAddr[nj] = b0 + nj * 16 * SROW * 2;
    }

    float acc[2][8][4];
    #pragma unroll
    for (int mi = 0; mi < 2; mi++)
        #pragma unroll
        for (int ni = 0; ni < 8; ni++)
            #pragma unroll
            for (int q = 0; q < 4; q++) acc[mi][ni][q] = 0.f;

    auto issue_chunk = [&](int buf, int kc) {
        const int k0 = kc * CH;
        #pragma unroll
        for (int it = 0; it < 2; it++) {
            int idx = tid + it * 256;
            int row = idx >> 2, q = idx & 3;
            cpasync16((unsigned)__cvta_generic_to_shared(&sA[buf][row][q * 8]),
                      g_z + (size_t)(rt * 128 + row) * ND + k0 + q * 8);
            cpasync16((unsigned)__cvta_generic_to_shared(&sB[buf][row][q * 8]),
                      g_z + (size_t)(ct * 128 + row) * ND + k0 + q * 8);
        }
        cpcommit();
    };

    issue_chunk(0, 0);
    for (int kc = 0; kc < ND / CH; kc++) {
        const int buf = kc & 1;
        if (kc < ND / CH - 1) { issue_chunk(buf ^ 1, kc + 1); cpwait<1>(); }
        else                  { cpwait<0>(); }
        __syncthreads();
        #pragma unroll
        for (int ks = 0; ks < 2; ks++) {
            const unsigned off = buf * BUFB + ks * 32;      // ks*16 cols * 2B
            unsigned af[2][4], bfr[8][2];
            ldsm4(af[0][0], af[0][1], af[0][2], af[0][3], aAddr[0] + off);
            ldsm4(af[1][0], af[1][1], af[1][2], af[1][3], aAddr[1] + off);
            #pragma unroll
            for (int nj = 0; nj < 4; nj++) {
                unsigned r0, r1, r2, r3;
                ldsm4(r0, r1, r2, r3, bAddr[nj] + off);
                bfr[2*nj][0] = r0; bfr[2*nj][1] = r1;
                bfr[2*nj+1][0] = r2; bfr[2*nj+1][1] = r3;
            }
            #pragma unroll
            for (int mi = 0; mi < 2; mi++)
                #pragma unroll
                for (int ni = 0; ni < 8; ni++)
                    mma16816(acc[mi][ni], af[mi], bfr[ni]);
        }
        __syncthreads();
    }

    // ---- epilogue: u = (d-1)*C1 (base-2); e = 2^u; row & col sums; neg min/max ----
    const float C1 = g_C1;
    float rA4[4] = {0,0,0,0}, rB4[4] = {0,0,0,0};
    float umin = __int_as_float(0x7f800000);
    float umax = __int_as_float(0xff800000);
    const int rowBase = rt * 128 + wr * 32;
    const int colBase = ct * 128 + wc * 64;
    #pragma unroll
    for (int ni = 0; ni < 8; ni++) {
        #pragma unroll
        for (int q = 0; q < 2; q++) {
            float cA = 0.f, cB = 0.f;
            const int jG = colBase + ni * 8 + 2 * c + q;
            #pragma unroll
            for (int mi = 0; mi < 2; mi++)
            #pragma unroll
            for (int p = 0; p < 2; p++) {
                const int ai = mi * 2 + p;
                float d = acc[mi][ni][p * 2 + q];
                float u = __fmaf_rn(d, C1, -C1);
                float e = ex2(u);
                float ue = u * e;
                rA4[ai] += e;  rB4[ai] += ue;
                cA += e;       cB += ue;
                if (!band) {
                    umin = fminf(umin, u); umax = fmaxf(umax, u);
                } else {
                    int iG = rowBase + mi * 16 + p * 8 + g;
                    int dd = (jG - iG) & (NB - 1);
                    if (isDiag) {
                        if (dd == 0)       g_uDiag[iG] = u;
                        else if (dd <= NK) g_uPos[iG * NK + dd - 1] = u;
                        else { umin = fminf(umin, u); umax = fmaxf(umax, u); }
                    } else {
                        // off-diag: the mirror entry is always a negative
                        if (dd <= NK)           g_uPos[iG * NK + dd - 1] = u;
                        else if (dd >= NB - NK) g_uPos[jG * NK + (NB - dd) - 1] = u;
                        umin = fminf(umin, u); umax = fmaxf(umax, u);
                    }
                }
            }
            if (!isDiag) {                                  // column sums (reduce over g)
                cA += __shfl_xor_sync(0xffffffffu, cA, 4);
                cA += __shfl_xor_sync(0xffffffffu, cA, 8);
                cA += __shfl_xor_sync(0xffffffffu, cA, 16);
                cB += __shfl_xor_sync(0xffffffffu, cB, 4);
                cB += __shfl_xor_sync(0xffffffffu, cB, 8);
                cB += __shfl_xor_sync(0xffffffffu, cB, 16);
                if (g == 0) {
                    int cl = wc * 64 + ni * 8 + 2 * c + q;
                    sColA[wr][cl] = cA; sColB[wr][cl] = cB;
                }
            }
        }
    }
    // row sums: reduce across the 4 lanes sharing a row (c = 0..3)
    #pragma unroll
    for (int ai = 0; ai < 4; ai++) {
        float a = rA4[ai], b = rB4[ai];
        a += __shfl_xor_sync(0xffffffffu, a, 1); a += __shfl_xor_sync(0xffffffffu, a, 2);
        b += __shfl_xor_sync(0xffffffffu, b, 1); b += __shfl_xor_sync(0xffffffffu, b, 2);
        if (c == 0) {
            int rloc = wr * 32 + (ai >> 1) * 16 + (ai & 1) * 8 + g;
            sRowA[wc][rloc] = a; sRowB[wc][rloc] = b;
        }
    }
    #pragma unroll
    for (int off = 16; off; off >>= 1) {
        umin = fminf(umin, __shfl_xor_sync(0xffffffffu, umin, off));
        umax = fmaxf(umax, __shfl_xor_sync(0xffffffffu, umax, off));
    }
    if (lane == 0) { sMin[w] = umin; sMax[w] = umax; }
    __syncthreads();
    if (tid < 128) {
        g_Apart[ct * NB + rt * 128 + tid] = sRowA[0][tid] + sRowA[1][tid];
        g_Bpart[ct * NB + rt * 128 + tid] = sRowB[0][tid] + sRowB[1][tid];
        if (!isDiag) {
            g_Apart[rt * NB + ct * 128 + tid] =
                sColA[0][tid] + sColA[1][tid] + sColA[2][tid] + sColA[3][tid];
            g_Bpart[rt * NB + ct * 128 + tid] =
                sColB[0][tid] + sColB[1][tid] + sColB[2][tid] + sColB[3][tid];
        }
    }
    if (tid == 0) {
        float mn = sMin[0], mx = sMax[0];
        #pragma unroll
        for (int i = 1; i < 8; i++) { mn = fminf(mn, sMin[i]); mx = fmaxf(mx, sMax[i]); }
        atomicMin(&g_negMinK, enc(mn));
        atomicMax(&g_negMaxK, enc(mx));
    }
}

// ---------------- kernel 4: per-row log-denominator + weighted pos partial sums ----------------
__global__ void k_fin1(const float* __restrict__ pv) {
    int i = blockIdx.x * 128 + threadIdx.x;
    float A = 0.f, Bp = 0.f;
    #pragma unroll 8
    for (int t = 0; t < NT; t++) {
        A  += g_Apart[t * NB + i];
        Bp += g_Bpart[t * NB + i];
    }
    float Bn   = Bp * LN2_F;
    float nmin = dec(g_negMinK) * LN2_F;
    float nmax = dec(g_negMaxK) * LN2_F;
    float uD = g_uDiag[i];
    float eD = ex2(uD);
    float u[NK];
    float sumE = eD, sumSE = uD * LN2_F * eD;
    #pragma unroll
    for (int k = 0; k < NK; k++) {
        u[k] = g_uPos[i * NK + k];
        float e = ex2(u[k]);
        sumE  += e;
        sumSE += u[k] * LN2_F * e;
    }
    float Aneg = A - sumE;
    float Bneg = Bn - sumSE;
    float ld = logf(A + (Bneg - nmin * Aneg) / (nmax - nmin + 1e-8f));

    float pvMax = dec(g_pvMaxK), pvMin = dec(g_pvMinK);
    float invPr = 1.f / ((pvMax - pvMin) + 1e-8f);
    float accv = 0.f;
    #pragma unroll
    for (int k = 0; k < NK; k++) {
        float pw = (pvMax - pv[i * NK + k]) * invPr;
        accv += (u[k] * LN2_F - ld) * pw;
    }
    #pragma unroll
    for (int off = 16; off; off >>= 1) accv += __shfl_xor_sync(0xffffffffu, accv, off);
    __shared__ float sp[4];
    int wi = threadIdx.x >> 5;
    if ((threadIdx.x & 31) == 0) sp[wi] = accv;
    __syncthreads();
    if (threadIdx.x == 0)
        g_red[blockIdx.x] = sp[0] + sp[1] + sp[2] + sp[3];
}

// ---------------- kernel 5: final scalar ----------------
__global__ void k_fin2(float* __restrict__ out) {
    float v = g_red[threadIdx.x];                           // 64 threads
    #pragma unroll
    for (int off = 16; off; off >>= 1) v += __shfl_xor_sync(0xffffffffu, v, off);
    __shared__ float s2[2];
    if ((threadIdx.x & 31) == 0) s2[threadIdx.x >> 5] = v;
    __syncthreads();
    if (threadIdx.x == 0)
        out[0] = -(s2[0] + s2[1]) * (1.f / (NB * NK));
}

// ---------------- launch ----------------
extern "C" void kernel_launch(void* const* d_in, const int* in_sizes, int n_in,
                              void* d_out, int out_size) {
    const float* emb  = (const float*)d_in[0];
    const float* pv   = (const float*)d_in[1];
    const float* temp = (const float*)d_in[2];
    float* out = (float*)d_out;
    (void)in_sizes; (void)n_in; (void)out_size;

    k_init<<<1, 1>>>(temp);
    k_norm<<<NB / 8, 256>>>(emb);
    k_pvmm<<<NB * NK / (256 * 4), 256>>>(pv);
    k_main<<<dim3(NT, NT), 256>>>();
    k_fin1<<<NB / 128, 128>>>(pv);
    k_fin2<<<1, 64>>>(out);
}